// round 13
// baseline (speedup 1.0000x reference)
#include <cuda_runtime.h>
#include <math.h>

#define BB 4
#define NN 20480
#define KK 16
#define TOT (BB*NN)

typedef unsigned long long ull;

__device__ __forceinline__ ull pk2(float lo, float hi) {
    ull d; asm("mov.b64 %0,{%1,%2};" : "=l"(d) : "f"(lo), "f"(hi)); return d;
}
__device__ __forceinline__ float2 upk2(ull v) {
    float2 r; asm("mov.b64 {%0,%1},%2;" : "=f"(r.x), "=f"(r.y) : "l"(v)); return r;
}
__device__ __forceinline__ ull f2fma(ull a, ull b, ull c) {
    ull d; asm("fma.rn.f32x2 %0,%1,%2,%3;" : "=l"(d) : "l"(a), "l"(b), "l"(c)); return d;
}
__device__ __forceinline__ ull dup2(float v) { return pk2(v, v); }

__device__ float  g_feat0[TOT*16];
__device__ float  g_feat1[TOT*16];
__device__ float4 g_pstats[TOT];
__device__ float  g_gdis[TOT*16];
__device__ float  g_l1[TOT*256];
__device__ float  g_l2[TOT*256];
__device__ float  g_proj0[TOT*32];   // p1fc[:,2:18] @ feat0 per point (row = 128B)
__device__ float  g_proj1[TOT*32];   // p2fc[:,2:18] @ feat1 per point
__device__ float  g_A[64*32];
__device__ float  g_C[64*16];
__device__ float  g_M[64*4];
__device__ float  g_cv[64];
__device__ float2 g_A2[32*32];
__device__ float2 g_C2[16*32];
__device__ float2 g_M2[4*32];

// ---------------- kernel 0: fold linear tail ----------------
__global__ void k_fold(const float* __restrict__ m4W,
                       const float* __restrict__ m2W, const float* __restrict__ m2g, const float* __restrict__ m2b,
                       const float* __restrict__ scW, const float* __restrict__ scg, const float* __restrict__ scb,
                       const float* __restrict__ m3W, const float* __restrict__ m3g, const float* __restrict__ m3b) {
    int o = threadIdx.x;
    if (o < 64) {
        const float* wa = m4W + o*128;
        const float* wb = wa + 64;
        for (int j = 0; j < 32; j++) {
            float s = 0.f;
            for (int i = 0; i < 64; i++) s = fmaf(wa[i]*m2g[i], m2W[i*32+j], s);
            g_A[o*32+j] = s;
        }
        for (int j = 0; j < 16; j++) {
            float s = 0.f;
            for (int i = 0; i < 64; i++) s = fmaf(wa[i]*scg[i], scW[i*16+j], s);
            g_C[o*16+j] = s;
        }
        for (int j = 0; j < 4; j++) {
            float s = 0.f;
            for (int i = 0; i < 64; i++) s = fmaf(wb[i]*m3g[i], m3W[i*4+j], s);
            g_M[o*4+j] = s;
        }
        float s = 0.f;
        for (int i = 0; i < 64; i++) s += wa[i]*(m2b[i]+scb[i]) + wb[i]*m3b[i];
        g_cv[o] = s;
    }
    __syncthreads();
    if (o < 32) {
        for (int c = 0; c < 32; c++) g_A2[c*32+o] = make_float2(g_A[o*32+c], g_A[(o+32)*32+c]);
        for (int c = 0; c < 16; c++) g_C2[c*32+o] = make_float2(g_C[o*16+c], g_C[(o+32)*16+c]);
        for (int c = 0; c < 4;  c++) g_M2[c*32+o] = make_float2(g_M[o*4+c],  g_M[(o+32)*4+c]);
    }
}

// ---------------- kernel 1: per-point feat0 + stats + proj0 ----------------
__global__ void __launch_bounds__(256) k_point(
    const float* __restrict__ feature, const float* __restrict__ xyz,
    const int* __restrict__ nidx,
    const float* __restrict__ m1W, const float* __restrict__ m1g, const float* __restrict__ m1b,
    const float* __restrict__ p1fc) {
    __shared__ float s_w[16*17];
    __shared__ float s_pw[32*17];
    __shared__ float s_f0[8][16];
    int t = threadIdx.x;
    if (t < 256) s_w[(t>>4)*17 + (t&15)] = m1W[t];
    for (int i = t; i < 32*17; i += 256) { int o=i/17, c=i-o*17; s_pw[i] = (c<16)? p1fc[o*34+2+c] : 0.f; }
    __syncthreads();
    int wl = t>>5;
    int point = blockIdx.x*8 + wl;
    int lane  = t & 31;
    int b = point / NN, n = point - b*NN;
    const float* xb = xyz + (size_t)b*NN*3;
    float px = xb[n*3+0], py = xb[n*3+1], pz = xb[n*3+2];
    if (lane < 16) {
        int id = nidx[(size_t)point*16 + lane];
        float nx = xb[id*3+0], ny = xb[id*3+1], nz = xb[id*3+2];
        float rx = px-nx, ry = py-ny, rz = pz-nz;
        float rd = sqrtf(rx*rx + ry*ry + rz*rz);
        float m = rd, sx = nx, sy = ny, sz = nz;
        #pragma unroll
        for (int off = 8; off > 0; off >>= 1) {
            m  = fmaxf(m, __shfl_xor_sync(0xFFFFu, m,  off));
            sx += __shfl_xor_sync(0xFFFFu, sx, off);
            sy += __shfl_xor_sync(0xFFFFu, sy, off);
            sz += __shfl_xor_sync(0xFFFFu, sz, off);
        }
        if (lane == 0) {
            float mx = sx*(1.f/16.f), my = sy*(1.f/16.f), mz = sz*(1.f/16.f);
            float dx = px-mx, dy = py-my, dz = pz-mz;
            float da = atan2f(dy, dx);
            float db = atan2f(dz, sqrtf(dx*dx + dy*dy));
            float g2 = px*px + py*py + pz*pz;
            float gv = g2 * sqrtf(g2);
            g_pstats[point] = make_float4(da, db, (m*m*m)/gv, 0.f);
        }
    } else {
        int c = lane - 16;
        const float* fb = feature + ((size_t)b*16)*NN + n;
        float acc = 0.f;
        #pragma unroll
        for (int j = 0; j < 16; j++) acc = fmaf(s_w[c*17+j], fb[(size_t)j*NN], acc);
        float f = fmaxf(fmaf(m1g[c], acc, m1b[c]), 0.f);
        g_feat0[(size_t)point*16 + c] = f;
        s_f0[wl][c] = f;
    }
    __syncwarp();
    float pa = 0.f;
    #pragma unroll
    for (int c = 0; c < 16; c++) pa = fmaf(s_pw[lane*17+c], s_f0[wl][c], pa);
    g_proj0[(size_t)point*32 + lane] = pa;
}

// ---------------- kernel 2: geometry + lrep1 + lrep2 precompute ----------------
__global__ void __launch_bounds__(256) k_geom(
    const float* __restrict__ xyz, const int* __restrict__ nidx,
    const float* __restrict__ lm1W, const float* __restrict__ lm1g, const float* __restrict__ lm1b,
    const float* __restrict__ lm2W, const float* __restrict__ lm2g, const float* __restrict__ lm2b) {
    __shared__ float s_l1w[160], s_l1g[16], s_l1b[16];
    __shared__ float s_l2w[256], s_l2g[16], s_l2b[16];
    int t = threadIdx.x;
    for (int i = t; i < 160; i += 256) { int j=i/10, c=i-j*10; s_l1w[i] = (c<9)? lm1W[j*9+c] : 0.f; }
    if (t < 256) s_l2w[t] = lm2W[t];
    if (t < 16) { s_l1g[t]=lm1g[t]; s_l1b[t]=lm1b[t]; s_l2g[t]=lm2g[t]; s_l2b[t]=lm2b[t]; }
    __syncthreads();
    int point = blockIdx.x*16 + (t>>4);
    int k = t & 15;
    int b = point / NN, n = point - b*NN;
    const float* xb = xyz + (size_t)b*NN*3;
    float px = xb[n*3+0], py = xb[n*3+1], pz = xb[n*3+2];
    float4 ps = g_pstats[point];
    int id = nidx[(size_t)point*16 + k];
    float nx = xb[id*3+0], ny = xb[id*3+1], nz = xb[id*3+2];
    float rx = px-nx, ry = py-ny, rz = pz-nz;
    float xy2 = rx*rx + ry*ry;
    float rd = sqrtf(xy2 + rz*rz);
    g_gdis[(size_t)point*16 + k] = __expf(-rd);
    float lr8 = nz;
    ull lp0 = pk2(atan2f(ry, rx) - ps.x, atan2f(rz, sqrtf(xy2)) - ps.y);
    ull lp1 = pk2(rd, px);
    ull lp2 = pk2(py, pz);
    ull lp3 = pk2(nx, ny);
    float l1[16];
    #pragma unroll
    for (int j = 0; j < 16; j++) {
        const ull* wr = (const ull*)(s_l1w + j*10);
        ull a = f2fma(wr[0], lp0, (ull)0);
        a = f2fma(wr[1], lp1, a);
        a = f2fma(wr[2], lp2, a);
        a = f2fma(wr[3], lp3, a);
        float2 u = upk2(a);
        float acc = u.x + u.y + s_l1w[j*10+8]*lr8;
        l1[j] = fmaxf(fmaf(s_l1g[j], acc, s_l1b[j]), 0.f);
    }
    float* o1 = g_l1 + (size_t)point*256 + k;
    #pragma unroll
    for (int c = 0; c < 16; c++) o1[c*16] = l1[c];
    ull lv[8];
    #pragma unroll
    for (int p = 0; p < 8; p++) lv[p] = pk2(l1[2*p], l1[2*p+1]);
    float* o2 = g_l2 + (size_t)point*256 + k;
    #pragma unroll
    for (int j = 0; j < 16; j++) {
        const ull* wr = (const ull*)(s_l2w + j*16);
        ull a = 0ull;
        #pragma unroll
        for (int p = 0; p < 8; p++) a = f2fma(wr[p], lv[p], a);
        float2 u = upk2(a);
        o2[j*16] = fmaxf(fmaf(s_l2g[j], u.x + u.y, s_l2b[j]), 0.f);
    }
}

#define VROW 20

// ---------------- kernel 3: pool 1 (proj-assisted logits) + proj1 ----------------
__global__ void __launch_bounds__(128, 8) k_pool1(
    const int* __restrict__ nidx,
    const float* __restrict__ p1fc,
    const float* __restrict__ p1mW, const float* __restrict__ p1mg, const float* __restrict__ p1mb,
    const float* __restrict__ p2fc) {
    __shared__ float s_fc[32*35];
    __shared__ float s_pm[512];
    __shared__ float s_pw2[32*17];
    __shared__ __align__(16) float s_vT[4][34*VROW];
    __shared__ float s_flc[4][32];
    __shared__ float s_pj[4][16][32];
    __shared__ int   s_id[4][16];
    __shared__ float s_f1[4][16];
    int t = threadIdx.x;
    for (int i = t; i < 32*35; i += 128) { int o=i/35, c=i-o*35; s_fc[i] = (c<34)? p1fc[o*34+c] : 0.f; }
    for (int i = t; i < 512; i += 128) s_pm[i] = p1mW[(i&15)*32 + (i>>4)];
    for (int i = t; i < 32*17; i += 128) { int o=i/17, c=i-o*17; s_pw2[i] = (c<16)? p2fc[o*34+2+c] : 0.f; }
    __syncthreads();
    int wl = t>>5, lane = t&31;
    int point = blockIdx.x*4 + wl;
    int b = point / NN;
    int k = lane & 15, h = lane >> 4;
    float* vt = s_vT[wl];
    if (lane < 16) s_id[wl][lane] = nidx[(size_t)point*16 + lane];
    {
        const float4* src = (const float4*)(g_l1 + (size_t)point*256);
        float4 a = src[lane], c2 = src[lane+32];
        int ca = lane>>2, qa = lane&3;
        *(float4*)(vt + (18+ca)*VROW + 4*qa) = a;
        *(float4*)(vt + (26+ca)*VROW + 4*qa) = c2;
        if (lane < 4) {
            float4 g = ((const float4*)(g_gdis + (size_t)point*16))[lane];
            *(float4*)(vt + 4*lane) = g;
        }
    }
    __syncwarp();
    // cooperative proj0 gather: each row is a contiguous 128B line (1 wf per LDG)
    #pragma unroll
    for (int kk = 0; kk < 16; kk++)
        s_pj[wl][kk][lane] = g_proj0[((size_t)(b*NN) + s_id[wl][kk])*32 + lane];
    if (h == 0) {
        int id = s_id[wl][k];
        const float4* fn4 = (const float4*)(g_feat0 + (size_t)(b*NN + id)*16);
        const float4* fs4 = (const float4*)(g_feat0 + (size_t)point*16);
        float sad = 0.f;
        #pragma unroll
        for (int q = 0; q < 4; q++) {
            float4 a = fn4[q], s = fs4[q];
            vt[(2+4*q+0)*VROW+k] = a.x; vt[(2+4*q+1)*VROW+k] = a.y;
            vt[(2+4*q+2)*VROW+k] = a.z; vt[(2+4*q+3)*VROW+k] = a.w;
            sad += fabsf(s.x-a.x) + fabsf(s.y-a.y) + fabsf(s.z-a.z) + fabsf(s.w-a.w);
        }
        vt[1*VROW+k] = 2.0f*__expf(-sad*(1.f/16.f));
    }
    __syncwarp();
    // logits: init from proj0, then 18 remaining channels {gdis, fdis, lrep x16}
    ull acc[8];
    #pragma unroll
    for (int p = 0; p < 8; p++) acc[p] = pk2(s_pj[wl][2*p][lane], s_pj[wl][2*p+1][lane]);
    #pragma unroll
    for (int cc = 0; cc < 18; cc++) {
        int c = (cc < 2) ? cc : (cc + 16);
        ull wp = dup2(s_fc[lane*35 + c]);
        const ulonglong2* rp = (const ulonglong2*)(vt + c*VROW);
        #pragma unroll
        for (int q = 0; q < 4; q++) {
            ulonglong2 u = rp[q];
            acc[2*q]   = f2fma(wp, u.x, acc[2*q]);
            acc[2*q+1] = f2fma(wp, u.y, acc[2*q+1]);
        }
    }
    float mx = -3.402823466e38f;
    #pragma unroll
    for (int p = 0; p < 8; p++) { float2 u = upk2(acc[p]); mx = fmaxf(mx, fmaxf(u.x, u.y)); }
    float den = 0.f;
    #pragma unroll
    for (int p = 0; p < 8; p++) {
        float2 u = upk2(acc[p]);
        u.x = __expf(u.x - mx); u.y = __expf(u.y - mx);
        den += u.x + u.y;
        acc[p] = pk2(u.x, u.y);
    }
    const float4* myrow = (const float4*)(vt + (2+lane)*VROW);
    float fl = 0.f;
    #pragma unroll
    for (int q = 0; q < 4; q++) {
        float4 v = myrow[q];
        float2 e0 = upk2(acc[2*q]), e1 = upk2(acc[2*q+1]);
        fl = fmaf(v.x, e0.x, fl); fl = fmaf(v.y, e0.y, fl);
        fl = fmaf(v.z, e1.x, fl); fl = fmaf(v.w, e1.y, fl);
    }
    s_flc[wl][lane] = fl / den;
    __syncwarp();
    if (lane < 16) {
        float a2 = 0.f;
        #pragma unroll
        for (int c = 0; c < 32; c++) a2 = fmaf(s_pm[c*16+lane], s_flc[wl][c], a2);
        float f1 = fmaxf(fmaf(p1mg[lane], a2, p1mb[lane]), 0.f);
        g_feat1[(size_t)point*16 + lane] = f1;
        s_f1[wl][lane] = f1;
    }
    __syncwarp();
    // proj1 for pool2
    float pa = 0.f;
    #pragma unroll
    for (int c = 0; c < 16; c++) pa = fmaf(s_pw2[lane*17+c], s_f1[wl][c], pa);
    g_proj1[(size_t)point*32 + lane] = pa;
}

// ---------------- kernel 4: pool 2 (proj-assisted) + fused tail ----------------
__global__ void __launch_bounds__(128, 8) k_pool2(
    const float* __restrict__ feature,
    const float* __restrict__ xyz, const int* __restrict__ nidx,
    const float* __restrict__ p2fc,
    const float* __restrict__ p2mW, const float* __restrict__ p2mg, const float* __restrict__ p2mb,
    const float* __restrict__ m4g, const float* __restrict__ m4b,
    float* __restrict__ out) {
    __shared__ float s_pmT[32*34], s_pg[32], s_pb[32];
    __shared__ float s_fc[32*35];
    __shared__ float s_cv[64], s_g4[64], s_b4[64];
    __shared__ __align__(16) float s_vT[4][34*VROW];
    __shared__ float s_flc[4][32], s_f2[4][32], s_ft[4][16];
    __shared__ float s_pj[4][16][32];
    __shared__ int   s_id[4][16];
    __shared__ float s_out[64][5];
    int t = threadIdx.x;
    for (int i = t; i < 32*34; i += 128) { int o=i/34, c=i-o*34; s_pmT[i] = (c<32)? p2mW[o*32+c] : 0.f; }
    if (t < 32) { s_pg[t]=p2mg[t]; s_pb[t]=p2mb[t]; }
    for (int i = t; i < 32*35; i += 128) { int o=i/35, c=i-o*35; s_fc[i] = (c<34)? p2fc[o*34+c] : 0.f; }
    if (t < 64) { s_cv[t]=g_cv[t]; s_g4[t]=m4g[t]; s_b4[t]=m4b[t]; }
    __syncthreads();
    int wl = t>>5, lane = t&31;
    int point = blockIdx.x*4 + wl;
    int b = point / NN, n = point - b*NN;
    int k = lane & 15, h = lane >> 4;
    const float* xb = xyz + (size_t)b*NN*3;
    float px = xb[n*3+0], py = xb[n*3+1], pz = xb[n*3+2];
    float4 ps = g_pstats[point];
    if (lane < 16) s_ft[wl][lane] = feature[((size_t)(b*16+lane))*NN + n];
    float* vt = s_vT[wl];
    if (lane < 16) s_id[wl][lane] = nidx[(size_t)point*16 + lane];
    {
        const float4* src = (const float4*)(g_l2 + (size_t)point*256);
        float4 a = src[lane], c2 = src[lane+32];
        int ca = lane>>2, qa = lane&3;
        *(float4*)(vt + (18+ca)*VROW + 4*qa) = a;
        *(float4*)(vt + (26+ca)*VROW + 4*qa) = c2;
        if (lane < 4) {
            float4 g = ((const float4*)(g_gdis + (size_t)point*16))[lane];
            *(float4*)(vt + 4*lane) = g;
        }
    }
    __syncwarp();
    #pragma unroll
    for (int kk = 0; kk < 16; kk++)
        s_pj[wl][kk][lane] = g_proj1[((size_t)(b*NN) + s_id[wl][kk])*32 + lane];
    if (h == 0) {
        int id = s_id[wl][k];
        const float4* fn4 = (const float4*)(g_feat1 + (size_t)(b*NN + id)*16);
        const float4* fs4 = (const float4*)(g_feat1 + (size_t)point*16);
        float sad = 0.f;
        #pragma unroll
        for (int q = 0; q < 4; q++) {
            float4 a = fn4[q], s = fs4[q];
            vt[(2+4*q+0)*VROW+k] = a.x; vt[(2+4*q+1)*VROW+k] = a.y;
            vt[(2+4*q+2)*VROW+k] = a.z; vt[(2+4*q+3)*VROW+k] = a.w;
            sad += fabsf(s.x-a.x) + fabsf(s.y-a.y) + fabsf(s.z-a.z) + fabsf(s.w-a.w);
        }
        vt[1*VROW+k] = 2.0f*__expf(-sad*(1.f/16.f));
    }
    __syncwarp();
    ull acc[8];
    #pragma unroll
    for (int p = 0; p < 8; p++) acc[p] = pk2(s_pj[wl][2*p][lane], s_pj[wl][2*p+1][lane]);
    #pragma unroll
    for (int cc = 0; cc < 18; cc++) {
        int c = (cc < 2) ? cc : (cc + 16);
        ull wp = dup2(s_fc[lane*35 + c]);
        const ulonglong2* rp = (const ulonglong2*)(vt + c*VROW);
        #pragma unroll
        for (int q = 0; q < 4; q++) {
            ulonglong2 u = rp[q];
            acc[2*q]   = f2fma(wp, u.x, acc[2*q]);
            acc[2*q+1] = f2fma(wp, u.y, acc[2*q+1]);
        }
    }
    float mx = -3.402823466e38f;
    #pragma unroll
    for (int p = 0; p < 8; p++) { float2 u = upk2(acc[p]); mx = fmaxf(mx, fmaxf(u.x, u.y)); }
    float den = 0.f;
    #pragma unroll
    for (int p = 0; p < 8; p++) {
        float2 u = upk2(acc[p]);
        u.x = __expf(u.x - mx); u.y = __expf(u.y - mx);
        den += u.x + u.y;
        acc[p] = pk2(u.x, u.y);
    }
    const float4* myrow = (const float4*)(vt + (2+lane)*VROW);
    float fl = 0.f;
    #pragma unroll
    for (int q = 0; q < 4; q++) {
        float4 v = myrow[q];
        float2 e0 = upk2(acc[2*q]), e1 = upk2(acc[2*q+1]);
        fl = fmaf(v.x, e0.x, fl); fl = fmaf(v.y, e0.y, fl);
        fl = fmaf(v.z, e1.x, fl); fl = fmaf(v.w, e1.y, fl);
    }
    s_flc[wl][lane] = fl / den;
    __syncwarp();
    // p2m
    {
        const ull* wr = (const ull*)(s_pmT + lane*34);
        const ull* fr = (const ull*)(s_flc[wl]);
        ull a = 0ull;
        #pragma unroll
        for (int p = 0; p < 16; p++) a = f2fma(wr[p], fr[p], a);
        float2 u = upk2(a);
        s_f2[wl][lane] = fmaxf(fmaf(s_pg[lane], u.x + u.y, s_pb[lane]), 0.f);
    }
    __syncwarp();
    // fused tail (round-9 per-warp form)
    ull at = pk2(s_cv[lane], s_cv[lane+32]);
    #pragma unroll
    for (int c = 0; c < 32; c++) {
        ull w2 = __ldg((const ull*)&g_A2[c*32+lane]);
        at = f2fma(w2, dup2(s_f2[wl][c]), at);
    }
    #pragma unroll
    for (int c = 0; c < 16; c++) {
        ull w2 = __ldg((const ull*)&g_C2[c*32+lane]);
        at = f2fma(w2, dup2(s_ft[wl][c]), at);
    }
    at = f2fma(__ldg((const ull*)&g_M2[0*32+lane]), dup2(px),   at);
    at = f2fma(__ldg((const ull*)&g_M2[1*32+lane]), dup2(py),   at);
    at = f2fma(__ldg((const ull*)&g_M2[2*32+lane]), dup2(pz),   at);
    at = f2fma(__ldg((const ull*)&g_M2[3*32+lane]), dup2(ps.z), at);
    float2 r = upk2(at);
    s_out[lane]   [wl] = fmaxf(fmaf(s_g4[lane],    r.x, s_b4[lane]),    0.f);
    s_out[lane+32][wl] = fmaxf(fmaf(s_g4[lane+32], r.y, s_b4[lane+32]), 0.f);
    __syncthreads();
    if (t < 64) {
        int b0 = (blockIdx.x*4) / NN;
        int n0 = blockIdx.x*4 - b0*NN;
        float4 v = make_float4(s_out[t][0], s_out[t][1], s_out[t][2], s_out[t][3]);
        *(float4*)(out + ((size_t)(b0*64 + t))*NN + n0) = v;
    }
}

// ---------------- launch ----------------
extern "C" void kernel_launch(void* const* d_in, const int* in_sizes, int n_in,
                              void* d_out, int out_size) {
    const float* feature = (const float*)d_in[0];
    const float* xyz     = (const float*)d_in[1];
    const float* m1W  = (const float*)d_in[2];
    const float* m1g  = (const float*)d_in[3];
    const float* m1b  = (const float*)d_in[4];
    const float* lm1W = (const float*)d_in[5];
    const float* lm1g = (const float*)d_in[6];
    const float* lm1b = (const float*)d_in[7];
    const float* lm2W = (const float*)d_in[8];
    const float* lm2g = (const float*)d_in[9];
    const float* lm2b = (const float*)d_in[10];
    const float* p1fc = (const float*)d_in[11];
    const float* p1mW = (const float*)d_in[12];
    const float* p1mg = (const float*)d_in[13];
    const float* p1mb = (const float*)d_in[14];
    const float* p2fc = (const float*)d_in[15];
    const float* p2mW = (const float*)d_in[16];
    const float* p2mg = (const float*)d_in[17];
    const float* p2mb = (const float*)d_in[18];
    const float* m2W  = (const float*)d_in[19];
    const float* m2g  = (const float*)d_in[20];
    const float* m2b  = (const float*)d_in[21];
    const float* scW  = (const float*)d_in[22];
    const float* scg  = (const float*)d_in[23];
    const float* scb  = (const float*)d_in[24];
    const float* m3W  = (const float*)d_in[25];
    const float* m3g  = (const float*)d_in[26];
    const float* m3b  = (const float*)d_in[27];
    const float* m4W  = (const float*)d_in[28];
    const float* m4g  = (const float*)d_in[29];
    const float* m4b  = (const float*)d_in[30];
    const int*  nidx  = (const int*)d_in[31];
    float* out = (float*)d_out;

    k_fold <<<1, 64>>>(m4W, m2W, m2g, m2b, scW, scg, scb, m3W, m3g, m3b);
    k_point<<<TOT/8, 256>>>(feature, xyz, nidx, m1W, m1g, m1b, p1fc);
    k_geom <<<TOT/16, 256>>>(xyz, nidx, lm1W, lm1g, lm1b, lm2W, lm2g, lm2b);
    k_pool1<<<TOT/4, 128>>>(nidx, p1fc, p1mW, p1mg, p1mb, p2fc);
    k_pool2<<<TOT/4, 128>>>(feature, xyz, nidx, p2fc, p2mW, p2mg, p2mb, m4g, m4b, out);
}

// round 15
// speedup vs baseline: 1.2529x; 1.2529x over previous
#include <cuda_runtime.h>
#include <math.h>

#define BB 4
#define NN 20480
#define KK 16
#define TOT (BB*NN)

typedef unsigned long long ull;

__device__ __forceinline__ ull pk2(float lo, float hi) {
    ull d; asm("mov.b64 %0,{%1,%2};" : "=l"(d) : "f"(lo), "f"(hi)); return d;
}
__device__ __forceinline__ float2 upk2(ull v) {
    float2 r; asm("mov.b64 {%0,%1},%2;" : "=f"(r.x), "=f"(r.y) : "l"(v)); return r;
}
__device__ __forceinline__ ull f2fma(ull a, ull b, ull c) {
    ull d; asm("fma.rn.f32x2 %0,%1,%2,%3;" : "=l"(d) : "l"(a), "l"(b), "l"(c)); return d;
}
__device__ __forceinline__ ull dup2(float v) { return pk2(v, v); }

// chunk-swizzled element index within a value row (VROW stride):
// float position kk of row r lives at ((kk>>2) ^ ((r>>3)&3))*4 + (kk&3)
__device__ __forceinline__ int vswz(int r, int kk) {
    return ((((kk >> 2) ^ (r >> 3)) & 3) << 2) | (kk & 3);
}

__device__ float  g_feat0[TOT*16];
__device__ float  g_feat1[TOT*16];
__device__ float4 g_pstats[TOT];
__device__ float  g_gdis[TOT*16];
__device__ float  g_l1[TOT*256];
__device__ float  g_l2[TOT*256];
__device__ float  g_A[64*32];
__device__ float  g_C[64*16];
__device__ float  g_M[64*4];
__device__ float  g_cv[64];
__device__ float2 g_A2[32*32];
__device__ float2 g_C2[16*32];
__device__ float2 g_M2[4*32];

// ---------------- kernel 0: fold linear tail ----------------
__global__ void k_fold(const float* __restrict__ m4W,
                       const float* __restrict__ m2W, const float* __restrict__ m2g, const float* __restrict__ m2b,
                       const float* __restrict__ scW, const float* __restrict__ scg, const float* __restrict__ scb,
                       const float* __restrict__ m3W, const float* __restrict__ m3g, const float* __restrict__ m3b) {
    int o = threadIdx.x;
    if (o < 64) {
        const float* wa = m4W + o*128;
        const float* wb = wa + 64;
        for (int j = 0; j < 32; j++) {
            float s = 0.f;
            for (int i = 0; i < 64; i++) s = fmaf(wa[i]*m2g[i], m2W[i*32+j], s);
            g_A[o*32+j] = s;
        }
        for (int j = 0; j < 16; j++) {
            float s = 0.f;
            for (int i = 0; i < 64; i++) s = fmaf(wa[i]*scg[i], scW[i*16+j], s);
            g_C[o*16+j] = s;
        }
        for (int j = 0; j < 4; j++) {
            float s = 0.f;
            for (int i = 0; i < 64; i++) s = fmaf(wb[i]*m3g[i], m3W[i*4+j], s);
            g_M[o*4+j] = s;
        }
        float s = 0.f;
        for (int i = 0; i < 64; i++) s += wa[i]*(m2b[i]+scb[i]) + wb[i]*m3b[i];
        g_cv[o] = s;
    }
    __syncthreads();
    if (o < 32) {
        for (int c = 0; c < 32; c++) g_A2[c*32+o] = make_float2(g_A[o*32+c], g_A[(o+32)*32+c]);
        for (int c = 0; c < 16; c++) g_C2[c*32+o] = make_float2(g_C[o*16+c], g_C[(o+32)*16+c]);
        for (int c = 0; c < 4;  c++) g_M2[c*32+o] = make_float2(g_M[o*4+c],  g_M[(o+32)*4+c]);
    }
}

// ---------------- kernel 1: per-point feat0 + stats ----------------
__global__ void __launch_bounds__(256) k_point(
    const float* __restrict__ feature, const float* __restrict__ xyz,
    const int* __restrict__ nidx,
    const float* __restrict__ m1W, const float* __restrict__ m1g, const float* __restrict__ m1b) {
    __shared__ float s_w[16*17];
    int t = threadIdx.x;
    if (t < 256) s_w[(t>>4)*17 + (t&15)] = m1W[t];
    __syncthreads();
    int point = blockIdx.x*8 + (t>>5);
    int lane  = t & 31;
    int b = point / NN, n = point - b*NN;
    const float* xb = xyz + (size_t)b*NN*3;
    float px = xb[n*3+0], py = xb[n*3+1], pz = xb[n*3+2];
    if (lane < 16) {
        int id = nidx[(size_t)point*16 + lane];
        float nx = xb[id*3+0], ny = xb[id*3+1], nz = xb[id*3+2];
        float rx = px-nx, ry = py-ny, rz = pz-nz;
        float rd = sqrtf(rx*rx + ry*ry + rz*rz);
        float m = rd, sx = nx, sy = ny, sz = nz;
        #pragma unroll
        for (int off = 8; off > 0; off >>= 1) {
            m  = fmaxf(m, __shfl_xor_sync(0xFFFFu, m,  off));
            sx += __shfl_xor_sync(0xFFFFu, sx, off);
            sy += __shfl_xor_sync(0xFFFFu, sy, off);
            sz += __shfl_xor_sync(0xFFFFu, sz, off);
        }
        if (lane == 0) {
            float mx = sx*(1.f/16.f), my = sy*(1.f/16.f), mz = sz*(1.f/16.f);
            float dx = px-mx, dy = py-my, dz = pz-mz;
            float da = atan2f(dy, dx);
            float db = atan2f(dz, sqrtf(dx*dx + dy*dy));
            float g2 = px*px + py*py + pz*pz;
            float gv = g2 * sqrtf(g2);
            g_pstats[point] = make_float4(da, db, (m*m*m)/gv, 0.f);
        }
    } else {
        int c = lane - 16;
        const float* fb = feature + ((size_t)b*16)*NN + n;
        float acc = 0.f;
        #pragma unroll
        for (int j = 0; j < 16; j++) acc = fmaf(s_w[c*17+j], fb[(size_t)j*NN], acc);
        g_feat0[(size_t)point*16 + c] = fmaxf(fmaf(m1g[c], acc, m1b[c]), 0.f);
    }
}

// ---------------- kernel 2: geometry + lrep1 + lrep2 precompute ----------------
__global__ void __launch_bounds__(256) k_geom(
    const float* __restrict__ xyz, const int* __restrict__ nidx,
    const float* __restrict__ lm1W, const float* __restrict__ lm1g, const float* __restrict__ lm1b,
    const float* __restrict__ lm2W, const float* __restrict__ lm2g, const float* __restrict__ lm2b) {
    __shared__ float s_l1w[160], s_l1g[16], s_l1b[16];
    __shared__ float s_l2w[256], s_l2g[16], s_l2b[16];
    int t = threadIdx.x;
    for (int i = t; i < 160; i += 256) { int j=i/10, c=i-j*10; s_l1w[i] = (c<9)? lm1W[j*9+c] : 0.f; }
    if (t < 256) s_l2w[t] = lm2W[t];
    if (t < 16) { s_l1g[t]=lm1g[t]; s_l1b[t]=lm1b[t]; s_l2g[t]=lm2g[t]; s_l2b[t]=lm2b[t]; }
    __syncthreads();
    int point = blockIdx.x*16 + (t>>4);
    int k = t & 15;
    int b = point / NN, n = point - b*NN;
    const float* xb = xyz + (size_t)b*NN*3;
    float px = xb[n*3+0], py = xb[n*3+1], pz = xb[n*3+2];
    float4 ps = g_pstats[point];
    int id = nidx[(size_t)point*16 + k];
    float nx = xb[id*3+0], ny = xb[id*3+1], nz = xb[id*3+2];
    float rx = px-nx, ry = py-ny, rz = pz-nz;
    float xy2 = rx*rx + ry*ry;
    float rd = sqrtf(xy2 + rz*rz);
    g_gdis[(size_t)point*16 + k] = __expf(-rd);
    float lr8 = nz;
    ull lp0 = pk2(atan2f(ry, rx) - ps.x, atan2f(rz, sqrtf(xy2)) - ps.y);
    ull lp1 = pk2(rd, px);
    ull lp2 = pk2(py, pz);
    ull lp3 = pk2(nx, ny);
    float l1[16];
    #pragma unroll
    for (int j = 0; j < 16; j++) {
        const ull* wr = (const ull*)(s_l1w + j*10);
        ull a = f2fma(wr[0], lp0, (ull)0);
        a = f2fma(wr[1], lp1, a);
        a = f2fma(wr[2], lp2, a);
        a = f2fma(wr[3], lp3, a);
        float2 u = upk2(a);
        float acc = u.x + u.y + s_l1w[j*10+8]*lr8;
        l1[j] = fmaxf(fmaf(s_l1g[j], acc, s_l1b[j]), 0.f);
    }
    float* o1 = g_l1 + (size_t)point*256 + k;
    #pragma unroll
    for (int c = 0; c < 16; c++) o1[c*16] = l1[c];
    ull lv[8];
    #pragma unroll
    for (int p = 0; p < 8; p++) lv[p] = pk2(l1[2*p], l1[2*p+1]);
    float* o2 = g_l2 + (size_t)point*256 + k;
    #pragma unroll
    for (int j = 0; j < 16; j++) {
        const ull* wr = (const ull*)(s_l2w + j*16);
        ull a = 0ull;
        #pragma unroll
        for (int p = 0; p < 8; p++) a = f2fma(wr[p], lv[p], a);
        float2 u = upk2(a);
        o2[j*16] = fmaxf(fmaf(s_l2g[j], u.x + u.y, s_l2b[j]), 0.f);
    }
}

#define VROW 20

// ---------------- kernel 3: pool 1 ----------------
__global__ void __launch_bounds__(128, 10) k_pool1(
    const int* __restrict__ nidx,
    const float* __restrict__ p1fc,
    const float* __restrict__ p1mW, const float* __restrict__ p1mg, const float* __restrict__ p1mb) {
    __shared__ float s_fc[32*34];    // natural stride-34 layout (even -> float2 pairs)
    __shared__ __align__(8) float s_pm[512];  // [(c2*16+o)*2+e] = p1mW[o*32+2c2+e]
    __shared__ __align__(16) float s_vT[4][34*VROW];
    __shared__ __align__(16) float s_flc[4][32];
    int t = threadIdx.x;
    for (int i = t; i < 32*34; i += 128) s_fc[i] = p1fc[i];
    for (int i = t; i < 512; i += 128) {
        int e = i & 1, x = i >> 1, o = x & 15, c2 = x >> 4;
        s_pm[i] = p1mW[o*32 + 2*c2 + e];
    }
    __syncthreads();
    int wl = t>>5, lane = t&31;
    int point = blockIdx.x*4 + wl;
    int b = point / NN;
    int k = lane & 15, h = lane >> 4;
    float* vt = s_vT[wl];
    // cooperative load: lrep1 rows 18..33 (swizzled chunks), gdis row 0 (sw=0)
    {
        const float4* src = (const float4*)(g_l1 + (size_t)point*256);
        float4 a = src[lane], c2v = src[lane+32];
        int ca = lane>>2, qa = lane&3;
        int r1 = 18+ca, r2 = 26+ca;
        *(float4*)(vt + r1*VROW + (((qa ^ (r1>>3)) & 3) << 2)) = a;
        *(float4*)(vt + r2*VROW + (((qa ^ (r2>>3)) & 3) << 2)) = c2v;
        if (lane < 4) {
            float4 g = ((const float4*)(g_gdis + (size_t)point*16))[lane];
            *(float4*)(vt + 4*lane) = g;   // row 0, sw=0
        }
    }
    if (h == 0) {
        int id = nidx[(size_t)point*16 + k];
        const float4* fn4 = (const float4*)(g_feat0 + (size_t)(b*NN + id)*16);
        const float4* fs4 = (const float4*)(g_feat0 + (size_t)point*16);
        float sad = 0.f;
        #pragma unroll
        for (int q = 0; q < 4; q++) {
            float4 a = fn4[q], s = fs4[q];
            int r0 = 2+4*q;
            vt[(r0+0)*VROW + vswz(r0+0, k)] = a.x;
            vt[(r0+1)*VROW + vswz(r0+1, k)] = a.y;
            vt[(r0+2)*VROW + vswz(r0+2, k)] = a.z;
            vt[(r0+3)*VROW + vswz(r0+3, k)] = a.w;
            sad += fabsf(s.x-a.x) + fabsf(s.y-a.y) + fabsf(s.z-a.z) + fabsf(s.w-a.w);
        }
        vt[1*VROW + k] = 2.0f*__expf(-sad*(1.f/16.f));   // row 1, sw=0
    }
    __syncwarp();
    // attention logits: lane=o, f32x2 over k-pairs; paired weight loads
    ull acc[8];
    #pragma unroll
    for (int p = 0; p < 8; p++) acc[p] = 0ull;
    #pragma unroll
    for (int c2 = 0; c2 < 17; c2++) {
        float2 wpr = *(const float2*)(s_fc + lane*34 + 2*c2);
        #pragma unroll
        for (int e = 0; e < 2; e++) {
            int c = 2*c2 + e;
            ull wp = dup2(e ? wpr.y : wpr.x);
            const ulonglong2* rp = (const ulonglong2*)(vt + c*VROW);
            int sw = (c >> 3) & 3;
            #pragma unroll
            for (int q = 0; q < 4; q++) {
                ulonglong2 u = rp[q ^ sw];
                acc[2*q]   = f2fma(wp, u.x, acc[2*q]);
                acc[2*q+1] = f2fma(wp, u.y, acc[2*q+1]);
            }
        }
    }
    float mx = -3.402823466e38f;
    #pragma unroll
    for (int p = 0; p < 8; p++) { float2 u = upk2(acc[p]); mx = fmaxf(mx, fmaxf(u.x, u.y)); }
    float den = 0.f;
    #pragma unroll
    for (int p = 0; p < 8; p++) {
        float2 u = upk2(acc[p]);
        u.x = __expf(u.x - mx); u.y = __expf(u.y - mx);
        den += u.x + u.y;
        acc[p] = pk2(u.x, u.y);
    }
    // weighted sum of own channel row (2+lane), swizzle-aware, conflict-free now
    float fl = 0.f;
    {
        int rm = 2 + lane, swm = (rm >> 3) & 3;
        #pragma unroll
        for (int q = 0; q < 4; q++) {
            float4 v = *(const float4*)(vt + rm*VROW + (((q ^ swm) & 3) << 2));
            float2 e0 = upk2(acc[2*q]), e1 = upk2(acc[2*q+1]);
            fl = fmaf(v.x, e0.x, fl); fl = fmaf(v.y, e0.y, fl);
            fl = fmaf(v.z, e1.x, fl); fl = fmaf(v.w, e1.y, fl);
        }
    }
    s_flc[wl][lane] = fl / den;
    __syncwarp();
    if (lane < 16) {
        float a2 = 0.f;
        #pragma unroll
        for (int c2 = 0; c2 < 16; c2++) {
            float2 w2 = *(const float2*)(s_pm + (c2*16 + lane)*2);
            float2 fv = *(const float2*)(s_flc[wl] + 2*c2);
            a2 = fmaf(w2.x, fv.x, a2);
            a2 = fmaf(w2.y, fv.y, a2);
        }
        g_feat1[(size_t)point*16 + lane] = fmaxf(fmaf(p1mg[lane], a2, p1mb[lane]), 0.f);
    }
}

// ---------------- kernel 4: pool 2 + fused tail ----------------
__global__ void __launch_bounds__(128, 10) k_pool2(
    const float* __restrict__ feature,
    const float* __restrict__ xyz, const int* __restrict__ nidx,
    const float* __restrict__ p2fc,
    const float* __restrict__ p2mW, const float* __restrict__ p2mg, const float* __restrict__ p2mb,
    const float* __restrict__ m4g, const float* __restrict__ m4b,
    float* __restrict__ out) {
    __shared__ float s_pmT[32*34], s_pg[32], s_pb[32];
    __shared__ float s_fc[32*34];
    __shared__ float s_cv[64], s_g4[64], s_b4[64];
    __shared__ __align__(16) float s_vT[4][34*VROW];
    __shared__ __align__(16) float s_flc[4][32];
    __shared__ float s_f2[4][32], s_ft[4][16];
    __shared__ float s_out[64][5];
    int t = threadIdx.x;
    for (int i = t; i < 32*34; i += 128) { int o=i/34, c=i-o*34; s_pmT[i] = (c<32)? p2mW[o*32+c] : 0.f; }
    if (t < 32) { s_pg[t]=p2mg[t]; s_pb[t]=p2mb[t]; }
    for (int i = t; i < 32*34; i += 128) s_fc[i] = p2fc[i];
    if (t < 64) { s_cv[t]=g_cv[t]; s_g4[t]=m4g[t]; s_b4[t]=m4b[t]; }
    __syncthreads();
    int wl = t>>5, lane = t&31;
    int point = blockIdx.x*4 + wl;
    int b = point / NN, n = point - b*NN;
    int k = lane & 15, h = lane >> 4;
    const float* xb = xyz + (size_t)b*NN*3;
    float px = xb[n*3+0], py = xb[n*3+1], pz = xb[n*3+2];
    float4 ps = g_pstats[point];
    if (lane < 16) s_ft[wl][lane] = feature[((size_t)(b*16+lane))*NN + n];
    float* vt = s_vT[wl];
    {
        const float4* src = (const float4*)(g_l2 + (size_t)point*256);
        float4 a = src[lane], c2v = src[lane+32];
        int ca = lane>>2, qa = lane&3;
        int r1 = 18+ca, r2 = 26+ca;
        *(float4*)(vt + r1*VROW + (((qa ^ (r1>>3)) & 3) << 2)) = a;
        *(float4*)(vt + r2*VROW + (((qa ^ (r2>>3)) & 3) << 2)) = c2v;
        if (lane < 4) {
            float4 g = ((const float4*)(g_gdis + (size_t)point*16))[lane];
            *(float4*)(vt + 4*lane) = g;
        }
    }
    if (h == 0) {
        int id = nidx[(size_t)point*16 + k];
        const float4* fn4 = (const float4*)(g_feat1 + (size_t)(b*NN + id)*16);
        const float4* fs4 = (const float4*)(g_feat1 + (size_t)point*16);
        float sad = 0.f;
        #pragma unroll
        for (int q = 0; q < 4; q++) {
            float4 a = fn4[q], s = fs4[q];
            int r0 = 2+4*q;
            vt[(r0+0)*VROW + vswz(r0+0, k)] = a.x;
            vt[(r0+1)*VROW + vswz(r0+1, k)] = a.y;
            vt[(r0+2)*VROW + vswz(r0+2, k)] = a.z;
            vt[(r0+3)*VROW + vswz(r0+3, k)] = a.w;
            sad += fabsf(s.x-a.x) + fabsf(s.y-a.y) + fabsf(s.z-a.z) + fabsf(s.w-a.w);
        }
        vt[1*VROW + k] = 2.0f*__expf(-sad*(1.f/16.f));
    }
    __syncwarp();
    ull acc[8];
    #pragma unroll
    for (int p = 0; p < 8; p++) acc[p] = 0ull;
    #pragma unroll
    for (int c2 = 0; c2 < 17; c2++) {
        float2 wpr = *(const float2*)(s_fc + lane*34 + 2*c2);
        #pragma unroll
        for (int e = 0; e < 2; e++) {
            int c = 2*c2 + e;
            ull wp = dup2(e ? wpr.y : wpr.x);
            const ulonglong2* rp = (const ulonglong2*)(vt + c*VROW);
            int sw = (c >> 3) & 3;
            #pragma unroll
            for (int q = 0; q < 4; q++) {
                ulonglong2 u = rp[q ^ sw];
                acc[2*q]   = f2fma(wp, u.x, acc[2*q]);
                acc[2*q+1] = f2fma(wp, u.y, acc[2*q+1]);
            }
        }
    }
    float mx = -3.402823466e38f;
    #pragma unroll
    for (int p = 0; p < 8; p++) { float2 u = upk2(acc[p]); mx = fmaxf(mx, fmaxf(u.x, u.y)); }
    float den = 0.f;
    #pragma unroll
    for (int p = 0; p < 8; p++) {
        float2 u = upk2(acc[p]);
        u.x = __expf(u.x - mx); u.y = __expf(u.y - mx);
        den += u.x + u.y;
        acc[p] = pk2(u.x, u.y);
    }
    float fl = 0.f;
    {
        int rm = 2 + lane, swm = (rm >> 3) & 3;
        #pragma unroll
        for (int q = 0; q < 4; q++) {
            float4 v = *(const float4*)(vt + rm*VROW + (((q ^ swm) & 3) << 2));
            float2 e0 = upk2(acc[2*q]), e1 = upk2(acc[2*q+1]);
            fl = fmaf(v.x, e0.x, fl); fl = fmaf(v.y, e0.y, fl);
            fl = fmaf(v.z, e1.x, fl); fl = fmaf(v.w, e1.y, fl);
        }
    }
    s_flc[wl][lane] = fl / den;
    __syncwarp();
    // p2m (unchanged, canonical since round 2)
    {
        const ull* wr = (const ull*)(s_pmT + lane*34);
        const ull* fr = (const ull*)(s_flc[wl]);
        ull a = 0ull;
        #pragma unroll
        for (int p = 0; p < 16; p++) a = f2fma(wr[p], fr[p], a);
        float2 u = upk2(a);
        s_f2[wl][lane] = fmaxf(fmaf(s_pg[lane], u.x + u.y, s_pb[lane]), 0.f);
    }
    __syncwarp();
    // fused tail (round-9 per-warp form)
    ull at = pk2(s_cv[lane], s_cv[lane+32]);
    #pragma unroll
    for (int c = 0; c < 32; c++) {
        ull w2 = __ldg((const ull*)&g_A2[c*32+lane]);
        at = f2fma(w2, dup2(s_f2[wl][c]), at);
    }
    #pragma unroll
    for (int c = 0; c < 16; c++) {
        ull w2 = __ldg((const ull*)&g_C2[c*32+lane]);
        at = f2fma(w2, dup2(s_ft[wl][c]), at);
    }
    at = f2fma(__ldg((const ull*)&g_M2[0*32+lane]), dup2(px),   at);
    at = f2fma(__ldg((const ull*)&g_M2[1*32+lane]), dup2(py),   at);
    at = f2fma(__ldg((const ull*)&g_M2[2*32+lane]), dup2(pz),   at);
    at = f2fma(__ldg((const ull*)&g_M2[3*32+lane]), dup2(ps.z), at);
    float2 r = upk2(at);
    s_out[lane]   [wl] = fmaxf(fmaf(s_g4[lane],    r.x, s_b4[lane]),    0.f);
    s_out[lane+32][wl] = fmaxf(fmaf(s_g4[lane+32], r.y, s_b4[lane+32]), 0.f);
    __syncthreads();
    if (t < 64) {
        int b0 = (blockIdx.x*4) / NN;
        int n0 = blockIdx.x*4 - b0*NN;
        float4 v = make_float4(s_out[t][0], s_out[t][1], s_out[t][2], s_out[t][3]);
        *(float4*)(out + ((size_t)(b0*64 + t))*NN + n0) = v;
    }
}

// ---------------- launch ----------------
extern "C" void kernel_launch(void* const* d_in, const int* in_sizes, int n_in,
                              void* d_out, int out_size) {
    const float* feature = (const float*)d_in[0];
    const float* xyz     = (const float*)d_in[1];
    const float* m1W  = (const float*)d_in[2];
    const float* m1g  = (const float*)d_in[3];
    const float* m1b  = (const float*)d_in[4];
    const float* lm1W = (const float*)d_in[5];
    const float* lm1g = (const float*)d_in[6];
    const float* lm1b = (const float*)d_in[7];
    const float* lm2W = (const float*)d_in[8];
    const float* lm2g = (const float*)d_in[9];
    const float* lm2b = (const float*)d_in[10];
    const float* p1fc = (const float*)d_in[11];
    const float* p1mW = (const float*)d_in[12];
    const float* p1mg = (const float*)d_in[13];
    const float* p1mb = (const float*)d_in[14];
    const float* p2fc = (const float*)d_in[15];
    const float* p2mW = (const float*)d_in[16];
    const float* p2mg = (const float*)d_in[17];
    const float* p2mb = (const float*)d_in[18];
    const float* m2W  = (const float*)d_in[19];
    const float* m2g  = (const float*)d_in[20];
    const float* m2b  = (const float*)d_in[21];
    const float* scW  = (const float*)d_in[22];
    const float* scg  = (const float*)d_in[23];
    const float* scb  = (const float*)d_in[24];
    const float* m3W  = (const float*)d_in[25];
    const float* m3g  = (const float*)d_in[26];
    const float* m3b  = (const float*)d_in[27];
    const float* m4W  = (const float*)d_in[28];
    const float* m4g  = (const float*)d_in[29];
    const float* m4b  = (const float*)d_in[30];
    const int*  nidx  = (const int*)d_in[31];
    float* out = (float*)d_out;

    k_fold <<<1, 64>>>(m4W, m2W, m2g, m2b, scW, scg, scb, m3W, m3g, m3b);
    k_point<<<TOT/8, 256>>>(feature, xyz, nidx, m1W, m1g, m1b);
    k_geom <<<TOT/16, 256>>>(xyz, nidx, lm1W, lm1g, lm1b, lm2W, lm2g, lm2b);
    k_pool1<<<TOT/4, 128>>>(nidx, p1fc, p1mW, p1mg, p1mb);
    k_pool2<<<TOT/4, 128>>>(feature, xyz, nidx, p2fc, p2mW, p2mg, p2mb, m4g, m4b, out);
}

// round 17
// speedup vs baseline: 1.5528x; 1.2393x over previous
#include <cuda_runtime.h>
#include <math.h>

#define BB 4
#define NN 20480
#define KK 16
#define TOT (BB*NN)

typedef unsigned long long ull;

__device__ __forceinline__ ull pk2(float lo, float hi) {
    ull d; asm("mov.b64 %0,{%1,%2};" : "=l"(d) : "f"(lo), "f"(hi)); return d;
}
__device__ __forceinline__ float2 upk2(ull v) {
    float2 r; asm("mov.b64 {%0,%1},%2;" : "=f"(r.x), "=f"(r.y) : "l"(v)); return r;
}
__device__ __forceinline__ ull f2fma(ull a, ull b, ull c) {
    ull d; asm("fma.rn.f32x2 %0,%1,%2,%3;" : "=l"(d) : "l"(a), "l"(b), "l"(c)); return d;
}
__device__ __forceinline__ ull dup2(float v) { return pk2(v, v); }

// chunk-swizzled element index within a value row (VROW stride)
__device__ __forceinline__ int vswz(int r, int kk) {
    return ((((kk >> 2) ^ (r >> 3)) & 3) << 2) | (kk & 3);
}

__device__ float  g_feat0[TOT*16];
__device__ float  g_feat1[TOT*16];
__device__ float4 g_pstats[TOT];
__device__ float  g_gdis[TOT*16];
__device__ float  g_l1[TOT*256];
__device__ float  g_l2[TOT*256];
__device__ float  g_A[64*32];
__device__ float  g_C[64*16];
__device__ float  g_M[64*4];
__device__ float  g_cv[64];
__device__ float2 g_A2[32*32];
__device__ float2 g_C2[16*32];
__device__ float2 g_M2[4*32];

// ---------------- kernel 0: fold linear tail ----------------
__global__ void k_fold(const float* __restrict__ m4W,
                       const float* __restrict__ m2W, const float* __restrict__ m2g, const float* __restrict__ m2b,
                       const float* __restrict__ scW, const float* __restrict__ scg, const float* __restrict__ scb,
                       const float* __restrict__ m3W, const float* __restrict__ m3g, const float* __restrict__ m3b) {
    int o = threadIdx.x;
    if (o < 64) {
        const float* wa = m4W + o*128;
        const float* wb = wa + 64;
        for (int j = 0; j < 32; j++) {
            float s = 0.f;
            for (int i = 0; i < 64; i++) s = fmaf(wa[i]*m2g[i], m2W[i*32+j], s);
            g_A[o*32+j] = s;
        }
        for (int j = 0; j < 16; j++) {
            float s = 0.f;
            for (int i = 0; i < 64; i++) s = fmaf(wa[i]*scg[i], scW[i*16+j], s);
            g_C[o*16+j] = s;
        }
        for (int j = 0; j < 4; j++) {
            float s = 0.f;
            for (int i = 0; i < 64; i++) s = fmaf(wb[i]*m3g[i], m3W[i*4+j], s);
            g_M[o*4+j] = s;
        }
        float s = 0.f;
        for (int i = 0; i < 64; i++) s += wa[i]*(m2b[i]+scb[i]) + wb[i]*m3b[i];
        g_cv[o] = s;
    }
    __syncthreads();
    if (o < 32) {
        for (int c = 0; c < 32; c++) g_A2[c*32+o] = make_float2(g_A[o*32+c], g_A[(o+32)*32+c]);
        for (int c = 0; c < 16; c++) g_C2[c*32+o] = make_float2(g_C[o*16+c], g_C[(o+32)*16+c]);
        for (int c = 0; c < 4;  c++) g_M2[c*32+o] = make_float2(g_M[o*4+c],  g_M[(o+32)*4+c]);
    }
}

// ---------------- kernel 1: per-point feat0 + stats ----------------
__global__ void __launch_bounds__(256) k_point(
    const float* __restrict__ feature, const float* __restrict__ xyz,
    const int* __restrict__ nidx,
    const float* __restrict__ m1W, const float* __restrict__ m1g, const float* __restrict__ m1b) {
    __shared__ float s_w[16*17];
    int t = threadIdx.x;
    if (t < 256) s_w[(t>>4)*17 + (t&15)] = m1W[t];
    __syncthreads();
    int point = blockIdx.x*8 + (t>>5);
    int lane  = t & 31;
    int b = point / NN, n = point - b*NN;
    const float* xb = xyz + (size_t)b*NN*3;
    float px = xb[n*3+0], py = xb[n*3+1], pz = xb[n*3+2];
    if (lane < 16) {
        int id = nidx[(size_t)point*16 + lane];
        float nx = xb[id*3+0], ny = xb[id*3+1], nz = xb[id*3+2];
        float rx = px-nx, ry = py-ny, rz = pz-nz;
        float rd = sqrtf(rx*rx + ry*ry + rz*rz);
        float m = rd, sx = nx, sy = ny, sz = nz;
        #pragma unroll
        for (int off = 8; off > 0; off >>= 1) {
            m  = fmaxf(m, __shfl_xor_sync(0xFFFFu, m,  off));
            sx += __shfl_xor_sync(0xFFFFu, sx, off);
            sy += __shfl_xor_sync(0xFFFFu, sy, off);
            sz += __shfl_xor_sync(0xFFFFu, sz, off);
        }
        if (lane == 0) {
            float mx = sx*(1.f/16.f), my = sy*(1.f/16.f), mz = sz*(1.f/16.f);
            float dx = px-mx, dy = py-my, dz = pz-mz;
            float da = atan2f(dy, dx);
            float db = atan2f(dz, sqrtf(dx*dx + dy*dy));
            float g2 = px*px + py*py + pz*pz;
            float gv = g2 * sqrtf(g2);
            g_pstats[point] = make_float4(da, db, (m*m*m)/gv, 0.f);
        }
    } else {
        int c = lane - 16;
        const float* fb = feature + ((size_t)b*16)*NN + n;
        float acc = 0.f;
        #pragma unroll
        for (int j = 0; j < 16; j++) acc = fmaf(s_w[c*17+j], fb[(size_t)j*NN], acc);
        g_feat0[(size_t)point*16 + c] = fmaxf(fmaf(m1g[c], acc, m1b[c]), 0.f);
    }
}

// ---------------- kernel 2: geometry + lrep1 + lrep2 precompute ----------------
__global__ void __launch_bounds__(256) k_geom(
    const float* __restrict__ xyz, const int* __restrict__ nidx,
    const float* __restrict__ lm1W, const float* __restrict__ lm1g, const float* __restrict__ lm1b,
    const float* __restrict__ lm2W, const float* __restrict__ lm2g, const float* __restrict__ lm2b) {
    __shared__ float s_l1w[160], s_l1g[16], s_l1b[16];
    __shared__ float s_l2w[256], s_l2g[16], s_l2b[16];
    int t = threadIdx.x;
    for (int i = t; i < 160; i += 256) { int j=i/10, c=i-j*10; s_l1w[i] = (c<9)? lm1W[j*9+c] : 0.f; }
    if (t < 256) s_l2w[t] = lm2W[t];
    if (t < 16) { s_l1g[t]=lm1g[t]; s_l1b[t]=lm1b[t]; s_l2g[t]=lm2g[t]; s_l2b[t]=lm2b[t]; }
    __syncthreads();
    int point = blockIdx.x*16 + (t>>4);
    int k = t & 15;
    int b = point / NN, n = point - b*NN;
    const float* xb = xyz + (size_t)b*NN*3;
    float px = xb[n*3+0], py = xb[n*3+1], pz = xb[n*3+2];
    float4 ps = g_pstats[point];
    int id = nidx[(size_t)point*16 + k];
    float nx = xb[id*3+0], ny = xb[id*3+1], nz = xb[id*3+2];
    float rx = px-nx, ry = py-ny, rz = pz-nz;
    float xy2 = rx*rx + ry*ry;
    float rd = sqrtf(xy2 + rz*rz);
    g_gdis[(size_t)point*16 + k] = __expf(-rd);
    float lr8 = nz;
    ull lp0 = pk2(atan2f(ry, rx) - ps.x, atan2f(rz, sqrtf(xy2)) - ps.y);
    ull lp1 = pk2(rd, px);
    ull lp2 = pk2(py, pz);
    ull lp3 = pk2(nx, ny);
    float l1[16];
    #pragma unroll
    for (int j = 0; j < 16; j++) {
        const ull* wr = (const ull*)(s_l1w + j*10);
        ull a = f2fma(wr[0], lp0, (ull)0);
        a = f2fma(wr[1], lp1, a);
        a = f2fma(wr[2], lp2, a);
        a = f2fma(wr[3], lp3, a);
        float2 u = upk2(a);
        float acc = u.x + u.y + s_l1w[j*10+8]*lr8;
        l1[j] = fmaxf(fmaf(s_l1g[j], acc, s_l1b[j]), 0.f);
    }
    float* o1 = g_l1 + (size_t)point*256 + k;
    #pragma unroll
    for (int c = 0; c < 16; c++) o1[c*16] = l1[c];
    ull lv[8];
    #pragma unroll
    for (int p = 0; p < 8; p++) lv[p] = pk2(l1[2*p], l1[2*p+1]);
    float* o2 = g_l2 + (size_t)point*256 + k;
    #pragma unroll
    for (int j = 0; j < 16; j++) {
        const ull* wr = (const ull*)(s_l2w + j*16);
        ull a = 0ull;
        #pragma unroll
        for (int p = 0; p < 8; p++) a = f2fma(wr[p], lv[p], a);
        float2 u = upk2(a);
        o2[j*16] = fmaxf(fmaf(s_l2g[j], u.x + u.y, s_l2b[j]), 0.f);
    }
}

#define VROW 20
#define VSZ  (34*VROW)

// ---------------- kernel 3: pool 1 (2 points per warp) ----------------
__global__ void __launch_bounds__(128, 6) k_pool1(
    const int* __restrict__ nidx,
    const float* __restrict__ p1fc,
    const float* __restrict__ p1mW, const float* __restrict__ p1mg, const float* __restrict__ p1mb) {
    __shared__ float s_fc[32*34];
    __shared__ __align__(8) float s_pm[512];   // [(c2*16+o)*2+e] = p1mW[o*32+2c2+e]
    __shared__ __align__(16) float s_vT[8][VSZ];
    __shared__ __align__(16) float s_flc[8][32];
    int t = threadIdx.x;
    for (int i = t; i < 32*34; i += 128) s_fc[i] = p1fc[i];
    for (int i = t; i < 512; i += 128) {
        int e = i & 1, x = i >> 1, o = x & 15, c2 = x >> 4;
        s_pm[i] = p1mW[o*32 + 2*c2 + e];
    }
    __syncthreads();
    int wl = t>>5, lane = t&31;
    int hp = lane >> 4, li = lane & 15;
    int point = blockIdx.x*8 + 2*wl + hp;       // this half-warp's point
    int b = point / NN;
    float* vt = s_vT[2*wl + hp];
    // cooperative lrep load (both points, full warp each)
    #pragma unroll
    for (int pt = 0; pt < 2; pt++) {
        int pp = blockIdx.x*8 + 2*wl + pt;
        const float4* src = (const float4*)(g_l1 + (size_t)pp*256);
        float4 a = src[lane], c2v = src[lane+32];
        float* vtp = s_vT[2*wl + pt];
        int ca = lane>>2, qa = lane&3;
        int r1 = 18+ca, r2 = 26+ca;
        *(float4*)(vtp + r1*VROW + (((qa ^ (r1>>3)) & 3) << 2)) = a;
        *(float4*)(vtp + r2*VROW + (((qa ^ (r2>>3)) & 3) << 2)) = c2v;
    }
    // gdis: both halves load their own point's row 0
    if (li < 4) {
        float4 g = ((const float4*)(g_gdis + (size_t)point*16))[li];
        *(float4*)(vt + 4*li) = g;
    }
    // gather: all 32 lanes; li = neighbor index k of this half's point
    {
        int id = nidx[(size_t)point*16 + li];
        const float4* fn4 = (const float4*)(g_feat0 + (size_t)(b*NN + id)*16);
        const float4* fs4 = (const float4*)(g_feat0 + (size_t)point*16);
        float sad = 0.f;
        #pragma unroll
        for (int q = 0; q < 4; q++) {
            float4 a = fn4[q], s = fs4[q];
            int r0 = 2+4*q;
            vt[(r0+0)*VROW + vswz(r0+0, li)] = a.x;
            vt[(r0+1)*VROW + vswz(r0+1, li)] = a.y;
            vt[(r0+2)*VROW + vswz(r0+2, li)] = a.z;
            vt[(r0+3)*VROW + vswz(r0+3, li)] = a.w;
            sad += fabsf(s.x-a.x) + fabsf(s.y-a.y) + fabsf(s.z-a.z) + fabsf(s.w-a.w);
        }
        vt[1*VROW + li] = 2.0f*__expf(-sad*(1.f/16.f));
    }
    __syncwarp();
    // logits: lane handles outputs (li, li+16) of its point; V loads serve both halves
    ull accA[8], accB[8];
    #pragma unroll
    for (int p = 0; p < 8; p++) { accA[p] = 0ull; accB[p] = 0ull; }
    #pragma unroll
    for (int c2 = 0; c2 < 17; c2++) {
        float2 wA = *(const float2*)(s_fc + li*34 + 2*c2);
        float2 wB = *(const float2*)(s_fc + (li+16)*34 + 2*c2);
        #pragma unroll
        for (int e = 0; e < 2; e++) {
            int c = 2*c2 + e;
            ull wpA = dup2(e ? wA.y : wA.x);
            ull wpB = dup2(e ? wB.y : wB.x);
            const ulonglong2* rp = (const ulonglong2*)(vt + c*VROW);
            int sw = (c >> 3) & 3;
            #pragma unroll
            for (int q = 0; q < 4; q++) {
                ulonglong2 u = rp[q ^ sw];
                accA[2*q]   = f2fma(wpA, u.x, accA[2*q]);
                accA[2*q+1] = f2fma(wpA, u.y, accA[2*q+1]);
                accB[2*q]   = f2fma(wpB, u.x, accB[2*q]);
                accB[2*q+1] = f2fma(wpB, u.y, accB[2*q+1]);
            }
        }
    }
    // softmax per output (identical per-output order as before)
    float mxA = -3.402823466e38f, mxB = -3.402823466e38f;
    #pragma unroll
    for (int p = 0; p < 8; p++) {
        float2 uA = upk2(accA[p]); mxA = fmaxf(mxA, fmaxf(uA.x, uA.y));
        float2 uB = upk2(accB[p]); mxB = fmaxf(mxB, fmaxf(uB.x, uB.y));
    }
    float denA = 0.f, denB = 0.f;
    #pragma unroll
    for (int p = 0; p < 8; p++) {
        float2 uA = upk2(accA[p]);
        uA.x = __expf(uA.x - mxA); uA.y = __expf(uA.y - mxA);
        denA += uA.x + uA.y;
        accA[p] = pk2(uA.x, uA.y);
        float2 uB = upk2(accB[p]);
        uB.x = __expf(uB.x - mxB); uB.y = __expf(uB.y - mxB);
        denB += uB.x + uB.y;
        accB[p] = pk2(uB.x, uB.y);
    }
    // weighted sums for own channel rows (2+li) and (2+li+16)
    float flA = 0.f, flB = 0.f;
    {
        int rA = 2 + li, swA = (rA >> 3) & 3;
        int rB = 18 + li, swB = (rB >> 3) & 3;
        #pragma unroll
        for (int q = 0; q < 4; q++) {
            float4 vA = *(const float4*)(vt + rA*VROW + (((q ^ swA) & 3) << 2));
            float2 e0 = upk2(accA[2*q]), e1 = upk2(accA[2*q+1]);
            flA = fmaf(vA.x, e0.x, flA); flA = fmaf(vA.y, e0.y, flA);
            flA = fmaf(vA.z, e1.x, flA); flA = fmaf(vA.w, e1.y, flA);
            float4 vB = *(const float4*)(vt + rB*VROW + (((q ^ swB) & 3) << 2));
            float2 f0 = upk2(accB[2*q]), f1 = upk2(accB[2*q+1]);
            flB = fmaf(vB.x, f0.x, flB); flB = fmaf(vB.y, f0.y, flB);
            flB = fmaf(vB.z, f1.x, flB); flB = fmaf(vB.w, f1.y, flB);
        }
    }
    s_flc[2*wl+hp][li]    = flA / denA;
    s_flc[2*wl+hp][li+16] = flB / denB;
    __syncwarp();
    // p1m: li = output, hp = point; weights broadcast across halves
    {
        float a2 = 0.f;
        const float* flc = s_flc[2*wl+hp];
        #pragma unroll
        for (int c2 = 0; c2 < 16; c2++) {
            float2 w2 = *(const float2*)(s_pm + (c2*16 + li)*2);
            float2 fv = *(const float2*)(flc + 2*c2);
            a2 = fmaf(w2.x, fv.x, a2);
            a2 = fmaf(w2.y, fv.y, a2);
        }
        g_feat1[(size_t)point*16 + li] = fmaxf(fmaf(p1mg[li], a2, p1mb[li]), 0.f);
    }
}

// ---------------- kernel 4: pool 2 (2 points per warp) + fused tail ----------------
__global__ void __launch_bounds__(128, 6) k_pool2(
    const float* __restrict__ feature,
    const float* __restrict__ xyz, const int* __restrict__ nidx,
    const float* __restrict__ p2fc,
    const float* __restrict__ p2mW, const float* __restrict__ p2mg, const float* __restrict__ p2mb,
    const float* __restrict__ m4g, const float* __restrict__ m4b,
    float* __restrict__ out) {
    __shared__ float s_pmT[32*34], s_pg[32], s_pb[32];
    __shared__ float s_fc[32*34];
    __shared__ float s_cv[64], s_g4[64], s_b4[64];
    __shared__ __align__(16) float s_vT[8][VSZ];
    __shared__ __align__(16) float s_flc[8][32];
    __shared__ float s_f2[8][32], s_ft[8][16];
    __shared__ float4 s_pp[8];
    __shared__ float s_out[64][9];
    int t = threadIdx.x;
    for (int i = t; i < 32*34; i += 128) { int o=i/34, c=i-o*34; s_pmT[i] = (c<32)? p2mW[o*32+c] : 0.f; }
    if (t < 32) { s_pg[t]=p2mg[t]; s_pb[t]=p2mb[t]; }
    for (int i = t; i < 32*34; i += 128) s_fc[i] = p2fc[i];
    if (t < 64) { s_cv[t]=g_cv[t]; s_g4[t]=m4g[t]; s_b4[t]=m4b[t]; }
    __syncthreads();
    int wl = t>>5, lane = t&31;
    int hp = lane >> 4, li = lane & 15;
    int point = blockIdx.x*8 + 2*wl + hp;
    int b = point / NN, n = point - b*NN;
    const float* xb = xyz + (size_t)b*NN*3;
    float4 ps = g_pstats[point];
    if (li == 0) s_pp[2*wl+hp] = make_float4(xb[n*3+0], xb[n*3+1], xb[n*3+2], ps.z);
    s_ft[2*wl+hp][li] = feature[((size_t)(b*16+li))*NN + n];
    float* vt = s_vT[2*wl + hp];
    #pragma unroll
    for (int pt = 0; pt < 2; pt++) {
        int pp = blockIdx.x*8 + 2*wl + pt;
        const float4* src = (const float4*)(g_l2 + (size_t)pp*256);
        float4 a = src[lane], c2v = src[lane+32];
        float* vtp = s_vT[2*wl + pt];
        int ca = lane>>2, qa = lane&3;
        int r1 = 18+ca, r2 = 26+ca;
        *(float4*)(vtp + r1*VROW + (((qa ^ (r1>>3)) & 3) << 2)) = a;
        *(float4*)(vtp + r2*VROW + (((qa ^ (r2>>3)) & 3) << 2)) = c2v;
    }
    if (li < 4) {
        float4 g = ((const float4*)(g_gdis + (size_t)point*16))[li];
        *(float4*)(vt + 4*li) = g;
    }
    {
        int id = nidx[(size_t)point*16 + li];
        const float4* fn4 = (const float4*)(g_feat1 + (size_t)(b*NN + id)*16);
        const float4* fs4 = (const float4*)(g_feat1 + (size_t)point*16);
        float sad = 0.f;
        #pragma unroll
        for (int q = 0; q < 4; q++) {
            float4 a = fn4[q], s = fs4[q];
            int r0 = 2+4*q;
            vt[(r0+0)*VROW + vswz(r0+0, li)] = a.x;
            vt[(r0+1)*VROW + vswz(r0+1, li)] = a.y;
            vt[(r0+2)*VROW + vswz(r0+2, li)] = a.z;
            vt[(r0+3)*VROW + vswz(r0+3, li)] = a.w;
            sad += fabsf(s.x-a.x) + fabsf(s.y-a.y) + fabsf(s.z-a.z) + fabsf(s.w-a.w);
        }
        vt[1*VROW + li] = 2.0f*__expf(-sad*(1.f/16.f));
    }
    __syncwarp();
    ull accA[8], accB[8];
    #pragma unroll
    for (int p = 0; p < 8; p++) { accA[p] = 0ull; accB[p] = 0ull; }
    #pragma unroll
    for (int c2 = 0; c2 < 17; c2++) {
        float2 wA = *(const float2*)(s_fc + li*34 + 2*c2);
        float2 wB = *(const float2*)(s_fc + (li+16)*34 + 2*c2);
        #pragma unroll
        for (int e = 0; e < 2; e++) {
            int c = 2*c2 + e;
            ull wpA = dup2(e ? wA.y : wA.x);
            ull wpB = dup2(e ? wB.y : wB.x);
            const ulonglong2* rp = (const ulonglong2*)(vt + c*VROW);
            int sw = (c >> 3) & 3;
            #pragma unroll
            for (int q = 0; q < 4; q++) {
                ulonglong2 u = rp[q ^ sw];
                accA[2*q]   = f2fma(wpA, u.x, accA[2*q]);
                accA[2*q+1] = f2fma(wpA, u.y, accA[2*q+1]);
                accB[2*q]   = f2fma(wpB, u.x, accB[2*q]);
                accB[2*q+1] = f2fma(wpB, u.y, accB[2*q+1]);
            }
        }
    }
    float mxA = -3.402823466e38f, mxB = -3.402823466e38f;
    #pragma unroll
    for (int p = 0; p < 8; p++) {
        float2 uA = upk2(accA[p]); mxA = fmaxf(mxA, fmaxf(uA.x, uA.y));
        float2 uB = upk2(accB[p]); mxB = fmaxf(mxB, fmaxf(uB.x, uB.y));
    }
    float denA = 0.f, denB = 0.f;
    #pragma unroll
    for (int p = 0; p < 8; p++) {
        float2 uA = upk2(accA[p]);
        uA.x = __expf(uA.x - mxA); uA.y = __expf(uA.y - mxA);
        denA += uA.x + uA.y;
        accA[p] = pk2(uA.x, uA.y);
        float2 uB = upk2(accB[p]);
        uB.x = __expf(uB.x - mxB); uB.y = __expf(uB.y - mxB);
        denB += uB.x + uB.y;
        accB[p] = pk2(uB.x, uB.y);
    }
    float flA = 0.f, flB = 0.f;
    {
        int rA = 2 + li, swA = (rA >> 3) & 3;
        int rB = 18 + li, swB = (rB >> 3) & 3;
        #pragma unroll
        for (int q = 0; q < 4; q++) {
            float4 vA = *(const float4*)(vt + rA*VROW + (((q ^ swA) & 3) << 2));
            float2 e0 = upk2(accA[2*q]), e1 = upk2(accA[2*q+1]);
            flA = fmaf(vA.x, e0.x, flA); flA = fmaf(vA.y, e0.y, flA);
            flA = fmaf(vA.z, e1.x, flA); flA = fmaf(vA.w, e1.y, flA);
            float4 vB = *(const float4*)(vt + rB*VROW + (((q ^ swB) & 3) << 2));
            float2 f0 = upk2(accB[2*q]), f1 = upk2(accB[2*q+1]);
            flB = fmaf(vB.x, f0.x, flB); flB = fmaf(vB.y, f0.y, flB);
            flB = fmaf(vB.z, f1.x, flB); flB = fmaf(vB.w, f1.y, flB);
        }
    }
    s_flc[2*wl+hp][li]    = flA / denA;
    s_flc[2*wl+hp][li+16] = flB / denB;
    __syncwarp();
    // p2m: lane = output o (0..31); weight loads shared across the warp's 2 points
    {
        const ull* wr  = (const ull*)(s_pmT + lane*34);
        const ull* frA = (const ull*)(s_flc[2*wl+0]);
        const ull* frB = (const ull*)(s_flc[2*wl+1]);
        ull aA = 0ull, aB = 0ull;
        #pragma unroll
        for (int p = 0; p < 16; p++) {
            ull w = wr[p];
            aA = f2fma(w, frA[p], aA);
            aB = f2fma(w, frB[p], aB);
        }
        float2 uA = upk2(aA), uB = upk2(aB);
        s_f2[2*wl+0][lane] = fmaxf(fmaf(s_pg[lane], uA.x + uA.y, s_pb[lane]), 0.f);
        s_f2[2*wl+1][lane] = fmaxf(fmaf(s_pg[lane], uB.x + uB.y, s_pb[lane]), 0.f);
    }
    __syncwarp();
    // fused tail: lane = output pair (lane, lane+32); weights loaded once, applied to both points
    {
        int pA = 2*wl + 0, pB = 2*wl + 1;
        float4 ppA = s_pp[pA], ppB = s_pp[pB];
        ull atA = pk2(s_cv[lane], s_cv[lane+32]);
        ull atB = atA;
        #pragma unroll
        for (int c = 0; c < 32; c++) {
            ull w2 = __ldg((const ull*)&g_A2[c*32+lane]);
            atA = f2fma(w2, dup2(s_f2[pA][c]), atA);
            atB = f2fma(w2, dup2(s_f2[pB][c]), atB);
        }
        #pragma unroll
        for (int c = 0; c < 16; c++) {
            ull w2 = __ldg((const ull*)&g_C2[c*32+lane]);
            atA = f2fma(w2, dup2(s_ft[pA][c]), atA);
            atB = f2fma(w2, dup2(s_ft[pB][c]), atB);
        }
        {
            ull w2;
            w2 = __ldg((const ull*)&g_M2[0*32+lane]);
            atA = f2fma(w2, dup2(ppA.x), atA); atB = f2fma(w2, dup2(ppB.x), atB);
            w2 = __ldg((const ull*)&g_M2[1*32+lane]);
            atA = f2fma(w2, dup2(ppA.y), atA); atB = f2fma(w2, dup2(ppB.y), atB);
            w2 = __ldg((const ull*)&g_M2[2*32+lane]);
            atA = f2fma(w2, dup2(ppA.z), atA); atB = f2fma(w2, dup2(ppB.z), atB);
            w2 = __ldg((const ull*)&g_M2[3*32+lane]);
            atA = f2fma(w2, dup2(ppA.w), atA); atB = f2fma(w2, dup2(ppB.w), atB);
        }
        float2 rA = upk2(atA), rB = upk2(atB);
        s_out[lane]   [pA] = fmaxf(fmaf(s_g4[lane],    rA.x, s_b4[lane]),    0.f);
        s_out[lane+32][pA] = fmaxf(fmaf(s_g4[lane+32], rA.y, s_b4[lane+32]), 0.f);
        s_out[lane]   [pB] = fmaxf(fmaf(s_g4[lane],    rB.x, s_b4[lane]),    0.f);
        s_out[lane+32][pB] = fmaxf(fmaf(s_g4[lane+32], rB.y, s_b4[lane+32]), 0.f);
    }
    __syncthreads();
    if (t < 64) {
        int b0 = (blockIdx.x*8) / NN;
        int n0 = blockIdx.x*8 - b0*NN;
        float* op = out + ((size_t)(b0*64 + t))*NN + n0;
        float4 v0 = make_float4(s_out[t][0], s_out[t][1], s_out[t][2], s_out[t][3]);
        float4 v1 = make_float4(s_out[t][4], s_out[t][5], s_out[t][6], s_out[t][7]);
        *(float4*)(op)     = v0;
        *(float4*)(op + 4) = v1;
    }
}

// ---------------- launch ----------------
extern "C" void kernel_launch(void* const* d_in, const int* in_sizes, int n_in,
                              void* d_out, int out_size) {
    const float* feature = (const float*)d_in[0];
    const float* xyz     = (const float*)d_in[1];
    const float* m1W  = (const float*)d_in[2];
    const float* m1g  = (const float*)d_in[3];
    const float* m1b  = (const float*)d_in[4];
    const float* lm1W = (const float*)d_in[5];
    const float* lm1g = (const float*)d_in[6];
    const float* lm1b = (const float*)d_in[7];
    const float* lm2W = (const float*)d_in[8];
    const float* lm2g = (const float*)d_in[9];
    const float* lm2b = (const float*)d_in[10];
    const float* p1fc = (const float*)d_in[11];
    const float* p1mW = (const float*)d_in[12];
    const float* p1mg = (const float*)d_in[13];
    const float* p1mb = (const float*)d_in[14];
    const float* p2fc = (const float*)d_in[15];
    const float* p2mW = (const float*)d_in[16];
    const float* p2mg = (const float*)d_in[17];
    const float* p2mb = (const float*)d_in[18];
    const float* m2W  = (const float*)d_in[19];
    const float* m2g  = (const float*)d_in[20];
    const float* m2b  = (const float*)d_in[21];
    const float* scW  = (const float*)d_in[22];
    const float* scg  = (const float*)d_in[23];
    const float* scb  = (const float*)d_in[24];
    const float* m3W  = (const float*)d_in[25];
    const float* m3g  = (const float*)d_in[26];
    const float* m3b  = (const float*)d_in[27];
    const float* m4W  = (const float*)d_in[28];
    const float* m4g  = (const float*)d_in[29];
    const float* m4b  = (const float*)d_in[30];
    const int*  nidx  = (const int*)d_in[31];
    float* out = (float*)d_out;

    k_fold <<<1, 64>>>(m4W, m2W, m2g, m2b, scW, scg, scb, m3W, m3g, m3b);
    k_point<<<TOT/8, 256>>>(feature, xyz, nidx, m1W, m1g, m1b);
    k_geom <<<TOT/16, 256>>>(xyz, nidx, lm1W, lm1g, lm1b, lm2W, lm2g, lm2b);
    k_pool1<<<TOT/8, 128>>>(nidx, p1fc, p1mW, p1mg, p1mb);
    k_pool2<<<TOT/8, 128>>>(feature, xyz, nidx, p2fc, p2mW, p2mg, p2mb, m4g, m4b, out);
}